// round 3
// baseline (speedup 1.0000x reference)
#include <cuda_runtime.h>
#include <math.h>
#include <stdint.h>

// Problem constants (match reference)
#define NN 100000
#define EE 600000
#define DD 128
#define RR 4
#define GG 256
#define CC 16

// ---------------- device scratch (no runtime alloc allowed) ----------------
// ya: [N, 640]  cols 0..127 = root-path output (scatter target), cols 128+r*128.. = h @ W_r
__device__ float g_ya[(size_t)NN * 640];          // 256 MB
__device__ float g_h0[(size_t)NN * DD];           // 51.2 MB
__device__ float g_h1[(size_t)NN * DD];           // 51.2 MB
__device__ int   g_cnt[NN * RR];                  // per (dst, rel) in-degree
__device__ float g_ew[EE];                        // per-edge weight 1/max(cnt,1)
__device__ float g_pool[GG * DD];
__device__ float g_pcnt[GG];

// ---------------- helpers ----------------
__device__ __forceinline__ void red_add_v4(float* addr, float x, float y, float z, float w) {
    asm volatile("red.global.add.v4.f32 [%0], {%1,%2,%3,%4};"
                 :: "l"(addr), "f"(x), "f"(y), "f"(z), "f"(w) : "memory");
}

__device__ __forceinline__ float elu1(float v) {
    return v > 0.0f ? v : expm1f(v);
}

// ---------------- zero scratch ----------------
__global__ void zero_kernel() {
    int i = blockIdx.x * blockDim.x + threadIdx.x;
    if (i < NN * RR) g_cnt[i] = 0;
    if (i < GG * DD) g_pool[i] = 0.0f;
    if (i < GG)      g_pcnt[i] = 0.0f;
}

// ---------------- degree count + edge weights ----------------
__global__ void count_kernel(const int* __restrict__ ei, const int* __restrict__ et) {
    int e = blockIdx.x * blockDim.x + threadIdx.x;
    if (e >= EE) return;
    atomicAdd(&g_cnt[ei[EE + e] * RR + et[e]], 1);
}

__global__ void ew_kernel(const int* __restrict__ ei, const int* __restrict__ et) {
    int e = blockIdx.x * blockDim.x + threadIdx.x;
    if (e >= EE) return;
    int c = g_cnt[ei[EE + e] * RR + et[e]];
    g_ew[e] = 1.0f / (float)(c > 1 ? c : 1);
}

// ---------------- GEMM: C[M,640] = A[M,128] x [Wroot | Wrel0..3] ----------------
__global__ __launch_bounds__(256) void gemm_kernel(
    const float* __restrict__ A, const float* __restrict__ Wroot,
    const float* __restrict__ Wrel, float* __restrict__ C, int M)
{
    const int bm = blockIdx.x;
    const int bn = blockIdx.y;
    const float* B = (bn == 0) ? Wroot : (Wrel + (size_t)(bn - 1) * DD * DD);

    __shared__ float As[16][128];   // [k][m]
    __shared__ float Bs[16][128];   // [k][n]

    const int tid = threadIdx.x;
    const int tx = tid & 15;   // n dir
    const int ty = tid >> 4;   // m dir
    const int row0 = bm * 128;

    float acc[8][8];
    #pragma unroll
    for (int i = 0; i < 8; i++)
        #pragma unroll
        for (int j = 0; j < 8; j++) acc[i][j] = 0.0f;

    for (int k0 = 0; k0 < DD; k0 += 16) {
        #pragma unroll
        for (int l = 0; l < 2; l++) {
            int idx = tid + l * 256;         // 0..511
            int m  = idx >> 2;               // 0..127
            int kg = idx & 3;                // 0..3
            int row = row0 + m;
            float4 v = make_float4(0.f, 0.f, 0.f, 0.f);
            if (row < M) v = *(const float4*)(A + (size_t)row * DD + k0 + kg * 4);
            As[kg * 4 + 0][m] = v.x;
            As[kg * 4 + 1][m] = v.y;
            As[kg * 4 + 2][m] = v.z;
            As[kg * 4 + 3][m] = v.w;
        }
        #pragma unroll
        for (int l = 0; l < 2; l++) {
            int idx = tid + l * 256;
            int kk = idx >> 5;               // 0..15
            int n4 = idx & 31;               // 0..31
            *(float4*)&Bs[kk][n4 * 4] = *(const float4*)(B + (size_t)(k0 + kk) * DD + n4 * 4);
        }
        __syncthreads();

        #pragma unroll
        for (int kk = 0; kk < 16; kk++) {
            float a[8], b[8];
            *(float4*)&a[0] = *(const float4*)&As[kk][ty * 8];
            *(float4*)&a[4] = *(const float4*)&As[kk][ty * 8 + 4];
            *(float4*)&b[0] = *(const float4*)&Bs[kk][tx * 8];
            *(float4*)&b[4] = *(const float4*)&Bs[kk][tx * 8 + 4];
            #pragma unroll
            for (int i = 0; i < 8; i++)
                #pragma unroll
                for (int j = 0; j < 8; j++)
                    acc[i][j] += a[i] * b[j];
        }
        __syncthreads();
    }

    const int colbase = bn * 128 + tx * 8;
    #pragma unroll
    for (int i = 0; i < 8; i++) {
        int row = row0 + ty * 8 + i;
        if (row < M) {
            float* cp = C + (size_t)row * 640 + colbase;
            *(float4*)cp       = make_float4(acc[i][0], acc[i][1], acc[i][2], acc[i][3]);
            *(float4*)(cp + 4) = make_float4(acc[i][4], acc[i][5], acc[i][6], acc[i][7]);
        }
    }
}

// ---------------- scatter: ya[dst, 0:128] += w_e * ya[src, 128+et*128 : +128] ----
__global__ __launch_bounds__(256) void scatter_kernel(
    const int* __restrict__ ei, const int* __restrict__ et)
{
    int warp = (blockIdx.x * blockDim.x + threadIdx.x) >> 5;
    int lane = threadIdx.x & 31;
    if (warp >= EE) return;
    int s = ei[warp];
    int d = ei[EE + warp];
    int t = et[warp];
    float w = g_ew[warp];
    const float4 v = *(const float4*)(g_ya + (size_t)s * 640 + 128 + t * 128 + lane * 4);
    float* dst = g_ya + (size_t)d * 640 + lane * 4;
    red_add_v4(dst, v.x * w, v.y * w, v.z * w, v.w * w);
}

// ---------------- elementwise: bias (+residual) (+BN+ELU) ----------------
// mode 0: bn+elu (layer 0) | mode 1: bn+elu + residual (layer 1) | mode 2: residual only
__global__ __launch_bounds__(256) void elem_kernel(
    const float* __restrict__ hin, const float* __restrict__ bias,
    const float* __restrict__ gamma, const float* __restrict__ beta,
    const float* __restrict__ mean, const float* __restrict__ var,
    float* __restrict__ hout, int mode)
{
    int idx = blockIdx.x * blockDim.x + threadIdx.x;
    if (idx >= NN * 32) return;
    int n  = idx >> 5;
    int c4 = (idx & 31) * 4;

    float4 v = *(const float4*)(g_ya + (size_t)n * 640 + c4);
    float4 bb = *(const float4*)(bias + c4);
    v.x += bb.x; v.y += bb.y; v.z += bb.z; v.w += bb.w;

    if (mode >= 1) {
        float4 hv = *(const float4*)(hin + (size_t)n * DD + c4);
        v.x += hv.x; v.y += hv.y; v.z += hv.z; v.w += hv.w;
    }
    if (mode <= 1) {
        float4 g  = *(const float4*)(gamma + c4);
        float4 be = *(const float4*)(beta + c4);
        float4 mu = *(const float4*)(mean + c4);
        float4 va = *(const float4*)(var + c4);
        v.x = elu1((v.x - mu.x) * rsqrtf(va.x + 1e-5f) * g.x + be.x);
        v.y = elu1((v.y - mu.y) * rsqrtf(va.y + 1e-5f) * g.y + be.y);
        v.z = elu1((v.z - mu.z) * rsqrtf(va.z + 1e-5f) * g.z + be.z);
        v.w = elu1((v.w - mu.w) * rsqrtf(va.w + 1e-5f) * g.w + be.w);
    }
    *(float4*)(hout + (size_t)n * DD + c4) = v;
}

// ---------------- pooling: warp handles 32 consecutive nodes (batch sorted) ----
__global__ __launch_bounds__(256) void pool_kernel(
    const float* __restrict__ h, const int* __restrict__ batch)
{
    int warp = (blockIdx.x * blockDim.x + threadIdx.x) >> 5;
    int lane = threadIdx.x & 31;
    int n0 = warp * 32;
    if (n0 >= NN) return;
    int nend = n0 + 32 < NN ? n0 + 32 : NN;

    float4 acc = make_float4(0.f, 0.f, 0.f, 0.f);
    int cur = batch[n0];
    int cnt = 0;
    for (int n = n0; n < nend; n++) {
        int b = batch[n];
        if (b != cur) {
            red_add_v4(g_pool + cur * DD + lane * 4, acc.x, acc.y, acc.z, acc.w);
            if (lane == 0) atomicAdd(&g_pcnt[cur], (float)cnt);
            acc = make_float4(0.f, 0.f, 0.f, 0.f);
            cnt = 0;
            cur = b;
        }
        float4 v = *(const float4*)(h + (size_t)n * DD + lane * 4);
        acc.x += v.x; acc.y += v.y; acc.z += v.z; acc.w += v.w;
        cnt++;
    }
    red_add_v4(g_pool + cur * DD + lane * 4, acc.x, acc.y, acc.z, acc.w);
    if (lane == 0) atomicAdd(&g_pcnt[cur], (float)cnt);
}

// ---------------- classifier head: 1 block per graph ----------------
__global__ __launch_bounds__(64) void head_kernel(
    const float* __restrict__ W1, const float* __restrict__ b1,
    const float* __restrict__ W2, const float* __restrict__ b2,
    float* __restrict__ out)
{
    int g = blockIdx.x;
    __shared__ float p[DD];
    __shared__ float z[64];
    __shared__ float lg[CC];

    float inv = 1.0f / fmaxf(g_pcnt[g], 1.0f);
    for (int d = threadIdx.x; d < DD; d += 64) p[d] = g_pool[g * DD + d] * inv;
    __syncthreads();

    int j = threadIdx.x;     // 0..63
    float s = b1[j];
    #pragma unroll 4
    for (int d = 0; d < DD; d++) s += p[d] * W1[d * 64 + j];
    z[j] = elu1(s);
    __syncthreads();

    if (j < CC) {
        float t = b2[j];
        #pragma unroll 4
        for (int k = 0; k < 64; k++) t += z[k] * W2[k * CC + j];
        lg[j] = t;
    }
    __syncthreads();

    if (j < CC) {
        float m = -1e30f;
        #pragma unroll
        for (int c = 0; c < CC; c++) m = fmaxf(m, lg[c]);
        float se = 0.0f;
        #pragma unroll
        for (int c = 0; c < CC; c++) se += expf(lg[c] - m);
        out[g * CC + j] = lg[j] - m - logf(se);
    }
}

// ---------------- launch ----------------
extern "C" void kernel_launch(void* const* d_in, const int* in_sizes, int n_in,
                              void* d_out, int out_size) {
    const float* x        = (const float*)d_in[0];
    const int*   ei       = (const int*)d_in[1];
    const int*   et       = (const int*)d_in[2];
    const int*   batch    = (const int*)d_in[3];
    const float* rel_w    = (const float*)d_in[4];   // [3,4,128,128]
    const float* root_w   = (const float*)d_in[5];   // [3,128,128]
    const float* bias     = (const float*)d_in[6];   // [3,128]
    const float* bn_gamma = (const float*)d_in[7];   // [2,128]
    const float* bn_beta  = (const float*)d_in[8];
    const float* bn_mean  = (const float*)d_in[9];
    const float* bn_var   = (const float*)d_in[10];
    const float* cls_w1   = (const float*)d_in[11];  // [128,64]
    const float* cls_b1   = (const float*)d_in[12];
    const float* cls_w2   = (const float*)d_in[13];  // [64,16]
    const float* cls_b2   = (const float*)d_in[14];
    float* out = (float*)d_out;

    void* p;
    cudaGetSymbolAddress(&p, g_ya);  float* YA = (float*)p;
    cudaGetSymbolAddress(&p, g_h0);  float* h0 = (float*)p;
    cudaGetSymbolAddress(&p, g_h1);  float* h1 = (float*)p;

    zero_kernel<<<(NN * RR + 255) / 256, 256>>>();
    count_kernel<<<(EE + 255) / 256, 256>>>(ei, et);
    ew_kernel<<<(EE + 255) / 256, 256>>>(ei, et);

    dim3 ggrid((NN + 127) / 128, 5);
    int sblocks = (int)(((size_t)EE * 32 + 255) / 256);
    int eblocks = (NN * 32 + 255) / 256;
    int pblocks = (((NN + 31) / 32) + 7) / 8;

    // layer 0: in = x -> h0
    gemm_kernel<<<ggrid, 256>>>(x, root_w, rel_w, YA, NN);
    scatter_kernel<<<sblocks, 256>>>(ei, et);
    elem_kernel<<<eblocks, 256>>>(nullptr, bias, bn_gamma, bn_beta, bn_mean, bn_var, h0, 0);

    // layer 1: in = h0 -> h1 (residual + BN1 + ELU)
    gemm_kernel<<<ggrid, 256>>>(h0, root_w + 1 * DD * DD,
                                rel_w + (size_t)1 * RR * DD * DD, YA, NN);
    scatter_kernel<<<sblocks, 256>>>(ei, et);
    elem_kernel<<<eblocks, 256>>>(h0, bias + 1 * DD,
                                  bn_gamma + DD, bn_beta + DD, bn_mean + DD, bn_var + DD,
                                  h1, 1);

    // layer 2: in = h1 -> h0 (residual only)
    gemm_kernel<<<ggrid, 256>>>(h1, root_w + 2 * DD * DD,
                                rel_w + (size_t)2 * RR * DD * DD, YA, NN);
    scatter_kernel<<<sblocks, 256>>>(ei, et);
    elem_kernel<<<eblocks, 256>>>(h1, bias + 2 * DD,
                                  bn_gamma, bn_beta, bn_mean, bn_var, h0, 2);

    // pool + head
    pool_kernel<<<pblocks, 256>>>(h0, batch);
    head_kernel<<<GG, 64>>>(cls_w1, cls_b1, cls_w2, cls_b2, out);
}